// round 13
// baseline (speedup 1.0000x reference)
#include <cuda_runtime.h>
#include <cuda_fp16.h>
#include <cstdint>

// ---------------- problem constants ----------------
#define BATCH 4
#define SEQ   4096
#define DIM   1024
#define HEADS 16
#define DHEAD 64
#define INNER 1024
#define MROWS (BATCH*SEQ)   // 16384
#define QKVN  (3*INNER)     // 3072
#define LN_EPS 1e-5f

// ---------------- scratch (device globals; no allocs allowed) ----------------
__device__ float g_kvp[64*8*64*64];            // kv split partials (fp32)
__device__ float g_o[MROWS*INNER];             // attention out (fp32), LN reads

// fp16 operand storage
__device__ __half g_xh[MROWS*DIM];             // A of GEMM1 (x) and GEMM2 (LN out)
__device__ __half g_w1h[QKVN*DIM];             // w_qkv^T [N][K]
__device__ __half g_w2h[DIM*DIM];              // w_out^T [N][K]
__device__ __half g_qh[BATCH*HEADS*SEQ*DHEAD];
__device__ __half g_kh[BATCH*HEADS*SEQ*DHEAD];
__device__ __half g_vh[BATCH*HEADS*SEQ*DHEAD];
__device__ __half g_kvth[64*64*64];            // kv^T  [bh][d][m]

// =====================================================================
// helpers
// =====================================================================
__device__ __forceinline__ uint32_t smem_u32(const void* p) {
    uint32_t a;
    asm("{ .reg .u64 t; cvta.to.shared.u64 t, %1; cvt.u32.u64 %0, t; }"
        : "=r"(a) : "l"(p));
    return a;
}

__device__ __forceinline__ void cpa16(uint32_t s, const void* g) {
    asm volatile("cp.async.cg.shared.global [%0], [%1], 16;"
                 :: "r"(s), "l"(__cvta_generic_to_global(g)) : "memory");
}
#define CP_COMMIT() asm volatile("cp.async.commit_group;" ::: "memory")
#define CP_WAIT(n)  asm volatile("cp.async.wait_group %0;" :: "n"(n) : "memory")

__device__ __forceinline__ void ldm_x4(uint32_t addr, uint32_t* r) {
    asm volatile("ldmatrix.sync.aligned.m8n8.x4.shared.b16 {%0,%1,%2,%3}, [%4];"
        : "=r"(r[0]), "=r"(r[1]), "=r"(r[2]), "=r"(r[3]) : "r"(addr));
}

__device__ __forceinline__ void mma16816h(float* d, const uint32_t* a, const uint32_t* b) {
    asm volatile("mma.sync.aligned.m16n8k16.row.col.f32.f16.f16.f32 "
        "{%0,%1,%2,%3}, {%4,%5,%6,%7}, {%8,%9}, {%0,%1,%2,%3};"
        : "+f"(d[0]), "+f"(d[1]), "+f"(d[2]), "+f"(d[3])
        : "r"(a[0]), "r"(a[1]), "r"(a[2]), "r"(a[3]), "r"(b[0]), "r"(b[1]));
}

__device__ __forceinline__ uint32_t pack2h(__half a, __half b) {
    __half2 t = __halves2half2(a, b);
    return *reinterpret_cast<uint32_t*>(&t);
}

// =====================================================================
// fused conversion kernel: one launch covers x, w_qkv^T, w_out^T
// =====================================================================
#define NBX (MROWS*DIM/1024)   // 16384
#define NB1 (96*32)            // 3072
#define NB2 (32*32)            // 1024

__global__ __launch_bounds__(256)
void cvt_all(const float* __restrict__ x,
             const float* __restrict__ w1,
             const float* __restrict__ w2)
{
    const int tid = threadIdx.x;
    int blk = blockIdx.x;

    if (blk < NBX) {
        long i = (long)blk*256 + tid;
        float4 v = ((const float4*)x)[i];
        ((uint2*)g_xh)[i] = make_uint2(
            pack2h(__float2half_rn(v.x), __float2half_rn(v.y)),
            pack2h(__float2half_rn(v.z), __float2half_rn(v.w)));
        return;
    }
    blk -= NBX;

    const float* in;
    __half* hi;
    int N, bx;
    if (blk < NB1) { in = w1; hi = g_w1h; N = QKVN; bx = blk; }
    else           { in = w2; hi = g_w2h; N = DIM;  bx = blk - NB1; }

    __shared__ float t[32][33];
    const int nblk_n = N / 32;
    const int n0 = (bx % nblk_n) * 32;
    const int k0 = (bx / nblk_n) * 32;

    #pragma unroll
    for (int i = 0; i < 4; i++) {
        int r = (tid >> 5) + i*8, c = tid & 31;
        t[r][c] = in[(long)(k0+r)*N + n0 + c];
    }
    __syncthreads();
    #pragma unroll
    for (int i = 0; i < 4; i++) {
        int a = (tid >> 5) + i*8;
        int b = tid & 31;
        hi[(long)(n0+a)*DIM + k0 + b] = __float2half_rn(t[b][a]);
    }
}

// =====================================================================
// fp16 mma.sync GEMM: CTA 128x128, *** 4 warps (128 thr), warp 64x64 ***
//   K-chunk 64, 3-stage cp.async, 2 CTAs/SM.
//   Read amplification halved: smem-BW balanced with MMA issue.
//   mode 0: relu + q/k/v fp16 scatter   (B = w1, Nall=3072)
//   mode 1: +bias, fp32 out row-major   (B = w2, Nall=1024)
// =====================================================================
#define ST_A 0
#define ST_B 16384
#define ST_SZ 32768
#define GEMM_SMEM (3*ST_SZ)    // 98304/CTA; 2 CTAs = 192KB
                               // epilogue stage 128*132*4 = 67584 fits

__global__ __launch_bounds__(128, 2)
void mma_gemm(const float* __restrict__ bias, float* __restrict__ Cout, int mode)
{
    extern __shared__ char smem[];
    const uint32_t sb = smem_u32(smem);
    const int tid  = threadIdx.x;
    const int lane = tid & 31, wid = tid >> 5;
    const int wm = wid >> 1, wn = wid & 1;          // 2 x 2 warps, 64x64 each
    const int m0 = blockIdx.y * 128;
    const int n0 = blockIdx.x * 128;

    const __half* Ah = g_xh;
    const __half* Bh = mode ? g_w2h : g_w1h;

    auto issue = [&](int chunk, int buf) {
        const uint32_t so = sb + buf*ST_SZ;
        const int kofs = chunk * 64;
        #pragma unroll
        for (int i = 0; i < 8; i++) {               // A: 1024 16B chunks / 128 thr
            int cid = tid + i*128;
            int row = cid >> 3, c16 = cid & 7;
            uint32_t off = row*128 + c16*16;
            uint32_t sw = off ^ ((off >> 3) & 0x70);
            cpa16(so + ST_A + sw, Ah + (long)(m0 + row)*DIM + kofs + c16*8);
        }
        #pragma unroll
        for (int i = 0; i < 8; i++) {               // B: 1024 16B chunks / 128 thr
            int cid = tid + i*128;
            int row = cid >> 3, c16 = cid & 7;
            uint32_t off = row*128 + c16*16;
            uint32_t sw = off ^ ((off >> 3) & 0x70);
            cpa16(so + ST_B + sw, Bh + (long)(n0 + row)*DIM + kofs + c16*8);
        }
        CP_COMMIT();
    };

    const int ra  = lane & 15;
    const int kba = ((lane >> 4) & 1) * 16;        // bytes
    const int nnb = (lane & 7) + ((lane >> 4) & 1)*8;
    const int kbb = ((lane >> 3) & 1) * 16;        // bytes

    float acc[4][8][4];
    #pragma unroll
    for (int a = 0; a < 4; a++)
        #pragma unroll
        for (int b = 0; b < 8; b++)
            #pragma unroll
            for (int d = 0; d < 4; d++) acc[a][b][d] = 0.f;

    issue(0, 0); issue(1, 1);

    int buf = 0, nbuf = 2;
    #pragma unroll 1
    for (int c = 0; c < 16; c++) {
        if (c < 15) { CP_WAIT(1); } else { CP_WAIT(0); }
        __syncthreads();
        if (c + 2 < 16) issue(c + 2, nbuf);

        const uint32_t so = sb + buf*ST_SZ;

        #pragma unroll
        for (int k16 = 0; k16 < 4; k16++) {
            uint32_t ah[4][4], bf[4][4];
            {
                const int ka = k16*32 + kba;
                #pragma unroll
                for (int mf = 0; mf < 4; mf++) {
                    uint32_t off = (uint32_t)(wm*64 + mf*16 + ra)*128 + ka;
                    uint32_t sw = off ^ ((off >> 3) & 0x70);
                    ldm_x4(so + ST_A + sw, ah[mf]);
                }
            }
            {
                const int kb = k16*32 + kbb;
                #pragma unroll
                for (int np = 0; np < 4; np++) {
                    uint32_t off = (uint32_t)(wn*64 + np*16 + nnb)*128 + kb;
                    uint32_t sw = off ^ ((off >> 3) & 0x70);
                    ldm_x4(so + ST_B + sw, bf[np]);
                }
            }
            #pragma unroll
            for (int mf = 0; mf < 4; mf++)
                #pragma unroll
                for (int nf = 0; nf < 8; nf++)
                    mma16816h(acc[mf][nf], ah[mf], &bf[nf >> 1][(nf & 1)*2]);
        }
        buf = (buf == 2) ? 0 : buf + 1;
        nbuf = (nbuf == 2) ? 0 : nbuf + 1;
    }
    __syncthreads();

    // ---- epilogue: stage fp32 in smem, coalesced out ----
    float* stg = (float*)smem;                      // [128][132]
    #pragma unroll
    for (int mf = 0; mf < 4; mf++)
        #pragma unroll
        for (int nf = 0; nf < 8; nf++) {
            int row = wm*64 + mf*16 + (lane >> 2);
            int col = wn*64 + nf*8 + (lane & 3)*2;
            stg[row*132 + col]       = acc[mf][nf][0];
            stg[row*132 + col + 1]   = acc[mf][nf][1];
            stg[(row+8)*132 + col]   = acc[mf][nf][2];
            stg[(row+8)*132 + col+1] = acc[mf][nf][3];
        }
    __syncthreads();

    #pragma unroll 1
    for (int i = 0; i < 32; i++) {
        int slot = tid + i*128;
        int row = slot >> 5, c4 = slot & 31;
        float4 v = *(const float4*)&stg[row*132 + c4*4];
        int gm = m0 + row;
        int gn = n0 + c4*4;
        if (mode == 0) {
            int part = gn >> 10;
            int inner = gn & 1023;
            int h = inner >> 6, d = inner & 63;
            int b = gm >> 12, s = gm & 4095;
            long dst = (((long)(b*16 + h))*4096 + s)*64 + d;
            if (part != 2) {
                v.x = fmaxf(v.x, 0.f); v.y = fmaxf(v.y, 0.f);
                v.z = fmaxf(v.z, 0.f); v.w = fmaxf(v.w, 0.f);
            }
            uint2 uh = make_uint2(
                pack2h(__float2half_rn(v.x), __float2half_rn(v.y)),
                pack2h(__float2half_rn(v.z), __float2half_rn(v.w)));
            if (part == 0)      *(uint2*)(g_qh+dst) = uh;
            else if (part == 1) *(uint2*)(g_kh+dst) = uh;
            else                *(uint2*)(g_vh+dst) = uh;
        } else {
            float4 bs = *(const float4*)(bias + gn);
            v.x += bs.x; v.y += bs.y; v.z += bs.z; v.w += bs.w;
            *(float4*)(Cout + (long)gm*DIM + gn) = v;
        }
    }
}

// =====================================================================
// kv partials: fp32 FFMA on converted fp16 k,v
// =====================================================================
__global__ __launch_bounds__(256)
void kv_partial()
{
    const int bh = blockIdx.x >> 3;
    const int split = blockIdx.x & 7;
    __shared__ float Ks[32][64];
    __shared__ float Vs[32][64];

    const int tid = threadIdx.x;
    const int tm = (tid >> 4) << 2;
    const int tn = (tid & 15) << 2;
    float acc[4][4] = {{0.f}};

    const long base = ((long)bh*SEQ + split*512)*DHEAD;

    for (int n0 = 0; n0 < 512; n0 += 32) {
        #pragma unroll
        for (int r = 0; r < 2; r++) {
            int idx = tid + r*256;
            int row = idx >> 4;
            int col = (idx & 15) << 2;
            long a = base + (long)(n0+row)*DHEAD + col;
            uint2 uk = *(const uint2*)(g_kh+a);
            uint2 uv = *(const uint2*)(g_vh+a);
            __half2 k0 = *reinterpret_cast<__half2*>(&uk.x);
            __half2 k1 = *reinterpret_cast<__half2*>(&uk.y);
            __half2 v0 = *reinterpret_cast<__half2*>(&uv.x);
            __half2 v1 = *reinterpret_cast<__half2*>(&uv.y);
            Ks[row][col+0] = __low2float(k0);  Ks[row][col+1] = __high2float(k0);
            Ks[row][col+2] = __low2float(k1);  Ks[row][col+3] = __high2float(k1);
            Vs[row][col+0] = __low2float(v0);  Vs[row][col+1] = __high2float(v0);
            Vs[row][col+2] = __low2float(v1);  Vs[row][col+3] = __high2float(v1);
        }
        __syncthreads();
        #pragma unroll
        for (int nn = 0; nn < 32; nn++) {
            float4 a = *(const float4*)&Ks[nn][tm];
            float4 b = *(const float4*)&Vs[nn][tn];
            float av[4] = {a.x,a.y,a.z,a.w};
            float bv[4] = {b.x,b.y,b.z,b.w};
            #pragma unroll
            for (int i = 0; i < 4; i++)
                #pragma unroll
                for (int j = 0; j < 4; j++)
                    acc[i][j] = fmaf(av[i], bv[j], acc[i][j]);
        }
        __syncthreads();
    }

    float* dst = g_kvp + (long)blockIdx.x*4096;
    #pragma unroll
    for (int i = 0; i < 4; i++)
        #pragma unroll
        for (int j = 0; j < 4; j++)
            dst[(tm+i)*64 + tn + j] = acc[i][j];
}

__global__ void kv_reduce()
{
    int idx = blockIdx.x*256 + threadIdx.x;
    int bh = idx >> 12;
    int rem = idx & 4095;
    int m = rem >> 6, d = rem & 63;
    float s = 0.f;
    #pragma unroll
    for (int sp = 0; sp < 8; sp++)
        s += g_kvp[((long)(bh*8 + sp))*4096 + rem];
    g_kvth[(long)bh*4096 + d*64 + m] = __float2half_rn(s);
}

// =====================================================================
// o = q @ kv per (b,h): fp16 single-term MMA, M=128 N=64 K=64
// =====================================================================
#define OS_Q 0
#define OS_B 16384

__global__ __launch_bounds__(256)
void o_mma()
{
    __shared__ char sm[34816];      // max(Q 16KB + KVT 8KB, stage 128*68*4=34816)
    const uint32_t sb = smem_u32(sm);
    const int tid = threadIdx.x;
    const int lane = tid & 31, wm = tid >> 5;       // 8 warps x (16m x 64n)
    const int bh = blockIdx.x >> 5;
    const int mt = blockIdx.x & 31;
    const int b = bh >> 4, h = bh & 15;

    const long qbase = ((long)bh*SEQ + mt*128)*DHEAD;
    #pragma unroll
    for (int i = 0; i < 4; i++) {
        int cid = tid + i*256;
        int row = cid >> 3, c16 = cid & 7;
        uint32_t off = row*128 + c16*16;
        uint32_t sw = off ^ ((off >> 3) & 0x70);
        cpa16(sb + OS_Q + sw, g_qh + qbase + (long)row*DHEAD + c16*8);
    }
    #pragma unroll
    for (int i = 0; i < 2; i++) {
        int cid = tid + i*256;
        int row = cid >> 3, c16 = cid & 7;
        uint32_t off = row*128 + c16*16;
        uint32_t sw = off ^ ((off >> 3) & 0x70);
        cpa16(sb + OS_B + sw, g_kvth + (long)bh*4096 + row*64 + c16*8);
    }
    CP_COMMIT();
    CP_WAIT(0);
    __syncthreads();

    float acc[8][4];
    #pragma unroll
    for (int i = 0; i < 8; i++)
        #pragma unroll
        for (int j = 0; j < 4; j++) acc[i][j] = 0.f;

    #pragma unroll
    for (int k16 = 0; k16 < 4; k16++) {
        uint32_t ah[4];
        {
            const int r  = lane & 15;
            const int kb = (k16*16 + ((lane >> 4) & 1)*8) * 2;
            uint32_t off = (uint32_t)(wm*16 + r)*128 + kb;
            uint32_t sw = off ^ ((off >> 3) & 0x70);
            ldm_x4(sb + OS_Q + sw, ah);
        }
        uint32_t bf[4][4];
        {
            const int nn = (lane & 7) + ((lane >> 4) & 1)*8;
            const int kb = (k16*16 + ((lane >> 3) & 1)*8) * 2;
            #pragma unroll
            for (int np = 0; np < 4; np++) {
                uint32_t off = (uint32_t)(np*16 + nn)*128 + kb;
                uint32_t sw = off ^ ((off >> 3) & 0x70);
                ldm_x4(sb + OS_B + sw, bf[np]);
            }
        }
        #pragma unroll
        for (int nf = 0; nf < 8; nf++)
            mma16816h(acc[nf], ah, &bf[nf >> 1][(nf & 1)*2]);
    }
    __syncthreads();

    float* stg = (float*)sm;                        // [128][68]
    #pragma unroll
    for (int nf = 0; nf < 8; nf++) {
        int row = wm*16 + (lane >> 2);
        int col = nf*8 + (lane & 3)*2;
        stg[row*68 + col]       = acc[nf][0];
        stg[row*68 + col + 1]   = acc[nf][1];
        stg[(row+8)*68 + col]   = acc[nf][2];
        stg[(row+8)*68 + col+1] = acc[nf][3];
    }
    __syncthreads();

    #pragma unroll
    for (int i = 0; i < 8; i++) {
        int slot = tid + i*256;
        int row = slot >> 4, c4 = slot & 15;
        float4 v = *(const float4*)&stg[row*68 + c4*4];
        *(float4*)(g_o + (long)(b*SEQ + mt*128 + row)*INNER + h*DHEAD + c4*4) = v;
    }
}

// =====================================================================
// LayerNorm: g_o fp32 -> fp16 into g_xh (A of GEMM2)
// =====================================================================
__global__ __launch_bounds__(256)
void layernorm_rows(const float* __restrict__ gamma, const float* __restrict__ beta)
{
    const float* p = g_o + (long)blockIdx.x*INNER;
    const int tid = threadIdx.x;

    float4 v = ((const float4*)p)[tid];
    float s  = v.x + v.y + v.z + v.w;
    float sq = v.x*v.x + v.y*v.y + v.z*v.z + v.w*v.w;

    #pragma unroll
    for (int o = 16; o > 0; o >>= 1) {
        s  += __shfl_down_sync(0xffffffffu, s,  o);
        sq += __shfl_down_sync(0xffffffffu, sq, o);
    }
    __shared__ float sh[16];
    __shared__ float mu_s, inv_s;
    int wid = tid >> 5, lane = tid & 31;
    if (lane == 0) { sh[wid] = s; sh[8 + wid] = sq; }
    __syncthreads();
    if (tid == 0) {
        float t = 0.f, tq = 0.f;
        #pragma unroll
        for (int i = 0; i < 8; i++) { t += sh[i]; tq += sh[8+i]; }
        float mu = t * (1.f/INNER);
        float var = tq * (1.f/INNER) - mu*mu;
        mu_s = mu;
        inv_s = rsqrtf(fmaxf(var, 0.f) + LN_EPS);
    }
    __syncthreads();

    float mu = mu_s, inv = inv_s;
    float4 g = ((const float4*)gamma)[tid];
    float4 bt = ((const float4*)beta)[tid];
    float f0 = (v.x - mu)*inv*g.x + bt.x;
    float f1 = (v.y - mu)*inv*g.y + bt.y;
    float f2 = (v.z - mu)*inv*g.z + bt.z;
    float f3 = (v.w - mu)*inv*g.w + bt.w;

    long i = (long)blockIdx.x*256 + tid;
    ((uint2*)g_xh)[i] = make_uint2(
        pack2h(__float2half_rn(f0), __float2half_rn(f1)),
        pack2h(__float2half_rn(f2), __float2half_rn(f3)));
}

// =====================================================================
// launcher
// =====================================================================
extern "C" void kernel_launch(void* const* d_in, const int* in_sizes, int n_in,
                              void* d_out, int out_size)
{
    const float* x     = (const float*)d_in[0];
    const float* w_qkv = (const float*)d_in[1];
    const float* gamma = (const float*)d_in[2];
    const float* beta  = (const float*)d_in[3];
    const float* w_out = (const float*)d_in[4];
    const float* b_out = (const float*)d_in[5];
    float* out = (float*)d_out;

    cudaFuncSetAttribute(mma_gemm, cudaFuncAttributeMaxDynamicSharedMemorySize, GEMM_SMEM);

    // 0: all conversions in one launch
    cvt_all<<<NBX + NB1 + NB2, 256>>>(x, w_qkv, w_out);

    // 1: qkv = x @ w_qkv + relu -> q/k/v fp16
    mma_gemm<<<dim3(QKVN/128, MROWS/128), 128, GEMM_SMEM>>>(nullptr, nullptr, 0);
    // 2-3: kv = relu(k)^T v -> kv^T fp16
    kv_partial<<<512, 256>>>();
    kv_reduce<<<1024, 256>>>();
    // 4: o = q @ kv  (fp16 tensor)
    o_mma<<<2048, 256>>>();
    // 5: LayerNorm -> fp16
    layernorm_rows<<<MROWS, 256>>>(gamma, beta);
    // 6: out = LN(o) @ w_out + b_out
    mma_gemm<<<dim3(DIM/128, MROWS/128), 128, GEMM_SMEM>>>(b_out, out, 1);
}

// round 14
// speedup vs baseline: 1.0601x; 1.0601x over previous
#include <cuda_runtime.h>
#include <cuda_fp16.h>
#include <cstdint>

// ---------------- problem constants ----------------
#define BATCH 4
#define SEQ   4096
#define DIM   1024
#define HEADS 16
#define DHEAD 64
#define INNER 1024
#define MROWS (BATCH*SEQ)   // 16384
#define QKVN  (3*INNER)     // 3072
#define LN_EPS 1e-5f

// ---------------- scratch (device globals; no allocs allowed) ----------------
__device__ float g_kvp[64*8*64*64];            // kv split partials (fp32)

// fp16 operand storage
__device__ __half g_xh[MROWS*DIM];             // A of GEMM1 (x) and GEMM2 (LN out)
__device__ __half g_w1h[QKVN*DIM];             // w_qkv^T [N][K]
__device__ __half g_w2h[DIM*DIM];              // w_out^T [N][K]
__device__ __half g_qh[BATCH*HEADS*SEQ*DHEAD];
__device__ __half g_kh[BATCH*HEADS*SEQ*DHEAD];
__device__ __half g_vh[BATCH*HEADS*SEQ*DHEAD];
__device__ __half g_kvth[64*64*64];            // kv^T  [bh][e][d] (out-col major)

// =====================================================================
// helpers
// =====================================================================
__device__ __forceinline__ uint32_t smem_u32(const void* p) {
    uint32_t a;
    asm("{ .reg .u64 t; cvta.to.shared.u64 t, %1; cvt.u32.u64 %0, t; }"
        : "=r"(a) : "l"(p));
    return a;
}

__device__ __forceinline__ void cpa16(uint32_t s, const void* g) {
    asm volatile("cp.async.cg.shared.global [%0], [%1], 16;"
                 :: "r"(s), "l"(__cvta_generic_to_global(g)) : "memory");
}
#define CP_COMMIT() asm volatile("cp.async.commit_group;" ::: "memory")
#define CP_WAIT(n)  asm volatile("cp.async.wait_group %0;" :: "n"(n) : "memory")

__device__ __forceinline__ void ldm_x4(uint32_t addr, uint32_t* r) {
    asm volatile("ldmatrix.sync.aligned.m8n8.x4.shared.b16 {%0,%1,%2,%3}, [%4];"
        : "=r"(r[0]), "=r"(r[1]), "=r"(r[2]), "=r"(r[3]) : "r"(addr));
}

__device__ __forceinline__ void mma16816h(float* d, const uint32_t* a, const uint32_t* b) {
    asm volatile("mma.sync.aligned.m16n8k16.row.col.f32.f16.f16.f32 "
        "{%0,%1,%2,%3}, {%4,%5,%6,%7}, {%8,%9}, {%0,%1,%2,%3};"
        : "+f"(d[0]), "+f"(d[1]), "+f"(d[2]), "+f"(d[3])
        : "r"(a[0]), "r"(a[1]), "r"(a[2]), "r"(a[3]), "r"(b[0]), "r"(b[1]));
}

__device__ __forceinline__ uint32_t pack2h(__half a, __half b) {
    __half2 t = __halves2half2(a, b);
    return *reinterpret_cast<uint32_t*>(&t);
}

// =====================================================================
// fused conversion kernel: one launch covers x, w_qkv^T, w_out^T
// =====================================================================
#define NBX (MROWS*DIM/1024)   // 16384
#define NB1 (96*32)            // 3072
#define NB2 (32*32)            // 1024

__global__ __launch_bounds__(256)
void cvt_all(const float* __restrict__ x,
             const float* __restrict__ w1,
             const float* __restrict__ w2)
{
    const int tid = threadIdx.x;
    int blk = blockIdx.x;

    if (blk < NBX) {
        long i = (long)blk*256 + tid;
        float4 v = ((const float4*)x)[i];
        ((uint2*)g_xh)[i] = make_uint2(
            pack2h(__float2half_rn(v.x), __float2half_rn(v.y)),
            pack2h(__float2half_rn(v.z), __float2half_rn(v.w)));
        return;
    }
    blk -= NBX;

    const float* in;
    __half* hi;
    int N, bx;
    if (blk < NB1) { in = w1; hi = g_w1h; N = QKVN; bx = blk; }
    else           { in = w2; hi = g_w2h; N = DIM;  bx = blk - NB1; }

    __shared__ float t[32][33];
    const int nblk_n = N / 32;
    const int n0 = (bx % nblk_n) * 32;
    const int k0 = (bx / nblk_n) * 32;

    #pragma unroll
    for (int i = 0; i < 4; i++) {
        int r = (tid >> 5) + i*8, c = tid & 31;
        t[r][c] = in[(long)(k0+r)*N + n0 + c];
    }
    __syncthreads();
    #pragma unroll
    for (int i = 0; i < 4; i++) {
        int a = (tid >> 5) + i*8;
        int b = tid & 31;
        hi[(long)(n0+a)*DIM + k0 + b] = __float2half_rn(t[b][a]);
    }
}

// =====================================================================
// fp16 mma.sync GEMM — R12 configuration (measured best):
//   CTA 128x128, 8 warps, warp 64x32, K-chunk 64, 3-stage, 2 CTAs/SM
//   mode 0: relu + q/k/v fp16 scatter   (B = w1, Nall=3072)
//   mode 1: +bias, fp32 out row-major   (B = w2, Nall=1024)
// =====================================================================
#define ST_A 0
#define ST_B 16384
#define ST_SZ 32768
#define GEMM_SMEM (3*ST_SZ)    // 98304/CTA; 2 CTAs = 192KB

__global__ __launch_bounds__(256, 2)
void mma_gemm(const float* __restrict__ bias, float* __restrict__ Cout, int mode)
{
    extern __shared__ char smem[];
    const uint32_t sb = smem_u32(smem);
    const int tid  = threadIdx.x;
    const int lane = tid & 31, wid = tid >> 5;
    const int wm = wid >> 2, wn = wid & 3;          // 2 x 4 warps, 64x32 each
    const int m0 = blockIdx.y * 128;
    const int n0 = blockIdx.x * 128;

    const __half* Ah = g_xh;
    const __half* Bh = mode ? g_w2h : g_w1h;

    auto issue = [&](int chunk, int buf) {
        const uint32_t so = sb + buf*ST_SZ;
        const int kofs = chunk * 64;
        #pragma unroll
        for (int i = 0; i < 4; i++) {
            int cid = tid + i*256;
            int row = cid >> 3, c16 = cid & 7;
            uint32_t off = row*128 + c16*16;
            uint32_t sw = off ^ ((off >> 3) & 0x70);
            cpa16(so + ST_A + sw, Ah + (long)(m0 + row)*DIM + kofs + c16*8);
        }
        #pragma unroll
        for (int i = 0; i < 4; i++) {
            int cid = tid + i*256;
            int row = cid >> 3, c16 = cid & 7;
            uint32_t off = row*128 + c16*16;
            uint32_t sw = off ^ ((off >> 3) & 0x70);
            cpa16(so + ST_B + sw, Bh + (long)(n0 + row)*DIM + kofs + c16*8);
        }
        CP_COMMIT();
    };

    const int ra  = lane & 15;
    const int kba = ((lane >> 4) & 1) * 16;
    const int nnb = (lane & 7) + ((lane >> 4) & 1)*8;
    const int kbb = ((lane >> 3) & 1) * 16;

    float acc[4][4][4];
    #pragma unroll
    for (int a = 0; a < 4; a++)
        #pragma unroll
        for (int b = 0; b < 4; b++)
            #pragma unroll
            for (int d = 0; d < 4; d++) acc[a][b][d] = 0.f;

    issue(0, 0); issue(1, 1);

    int buf = 0, nbuf = 2;
    #pragma unroll 1
    for (int c = 0; c < 16; c++) {
        if (c < 15) { CP_WAIT(1); } else { CP_WAIT(0); }
        __syncthreads();
        if (c + 2 < 16) issue(c + 2, nbuf);

        const uint32_t so = sb + buf*ST_SZ;

        #pragma unroll
        for (int k16 = 0; k16 < 4; k16++) {
            uint32_t ah[4][4], bf2[2][4];
            {
                const int ka = k16*32 + kba;
                #pragma unroll
                for (int mf = 0; mf < 4; mf++) {
                    uint32_t off = (uint32_t)(wm*64 + mf*16 + ra)*128 + ka;
                    uint32_t sw = off ^ ((off >> 3) & 0x70);
                    ldm_x4(so + ST_A + sw, ah[mf]);
                }
            }
            {
                const int kb = k16*32 + kbb;
                #pragma unroll
                for (int np = 0; np < 2; np++) {
                    uint32_t off = (uint32_t)(wn*32 + np*16 + nnb)*128 + kb;
                    uint32_t sw = off ^ ((off >> 3) & 0x70);
                    ldm_x4(so + ST_B + sw, bf2[np]);
                }
            }
            #pragma unroll
            for (int mf = 0; mf < 4; mf++)
                #pragma unroll
                for (int nf = 0; nf < 4; nf++)
                    mma16816h(acc[mf][nf], ah[mf], &bf2[nf >> 1][(nf & 1)*2]);
        }
        buf = (buf == 2) ? 0 : buf + 1;
        nbuf = (nbuf == 2) ? 0 : nbuf + 1;
    }
    __syncthreads();

    // ---- epilogue: stage fp32 in smem, coalesced out ----
    float* stg = (float*)smem;                      // [128][132]
    #pragma unroll
    for (int mf = 0; mf < 4; mf++)
        #pragma unroll
        for (int nf = 0; nf < 4; nf++) {
            int row = wm*64 + mf*16 + (lane >> 2);
            int col = wn*32 + nf*8 + (lane & 3)*2;
            stg[row*132 + col]       = acc[mf][nf][0];
            stg[row*132 + col + 1]   = acc[mf][nf][1];
            stg[(row+8)*132 + col]   = acc[mf][nf][2];
            stg[(row+8)*132 + col+1] = acc[mf][nf][3];
        }
    __syncthreads();

    #pragma unroll 1
    for (int i = 0; i < 16; i++) {
        int slot = tid + i*256;
        int row = slot >> 5, c4 = slot & 31;
        float4 v = *(const float4*)&stg[row*132 + c4*4];
        int gm = m0 + row;
        int gn = n0 + c4*4;
        if (mode == 0) {
            int part = gn >> 10;
            int inner = gn & 1023;
            int h = inner >> 6, d = inner & 63;
            int b = gm >> 12, s = gm & 4095;
            long dst = (((long)(b*16 + h))*4096 + s)*64 + d;
            if (part != 2) {
                v.x = fmaxf(v.x, 0.f); v.y = fmaxf(v.y, 0.f);
                v.z = fmaxf(v.z, 0.f); v.w = fmaxf(v.w, 0.f);
            }
            uint2 uh = make_uint2(
                pack2h(__float2half_rn(v.x), __float2half_rn(v.y)),
                pack2h(__float2half_rn(v.z), __float2half_rn(v.w)));
            if (part == 0)      *(uint2*)(g_qh+dst) = uh;
            else if (part == 1) *(uint2*)(g_kh+dst) = uh;
            else                *(uint2*)(g_vh+dst) = uh;
        } else {
            float4 bs = *(const float4*)(bias + gn);
            v.x += bs.x; v.y += bs.y; v.z += bs.z; v.w += bs.w;
            *(float4*)(Cout + (long)gm*DIM + gn) = v;
        }
    }
}

// =====================================================================
// kv partials: fp32 FFMA on converted fp16 k,v (unchanged)
// =====================================================================
__global__ __launch_bounds__(256)
void kv_partial()
{
    const int bh = blockIdx.x >> 3;
    const int split = blockIdx.x & 7;
    __shared__ float Ks[32][64];
    __shared__ float Vs[32][64];

    const int tid = threadIdx.x;
    const int tm = (tid >> 4) << 2;
    const int tn = (tid & 15) << 2;
    float acc[4][4] = {{0.f}};

    const long base = ((long)bh*SEQ + split*512)*DHEAD;

    for (int n0 = 0; n0 < 512; n0 += 32) {
        #pragma unroll
        for (int r = 0; r < 2; r++) {
            int idx = tid + r*256;
            int row = idx >> 4;
            int col = (idx & 15) << 2;
            long a = base + (long)(n0+row)*DHEAD + col;
            uint2 uk = *(const uint2*)(g_kh+a);
            uint2 uv = *(const uint2*)(g_vh+a);
            __half2 k0 = *reinterpret_cast<__half2*>(&uk.x);
            __half2 k1 = *reinterpret_cast<__half2*>(&uk.y);
            __half2 v0 = *reinterpret_cast<__half2*>(&uv.x);
            __half2 v1 = *reinterpret_cast<__half2*>(&uv.y);
            Ks[row][col+0] = __low2float(k0);  Ks[row][col+1] = __high2float(k0);
            Ks[row][col+2] = __low2float(k1);  Ks[row][col+3] = __high2float(k1);
            Vs[row][col+0] = __low2float(v0);  Vs[row][col+1] = __high2float(v0);
            Vs[row][col+2] = __low2float(v1);  Vs[row][col+3] = __high2float(v1);
        }
        __syncthreads();
        #pragma unroll
        for (int nn = 0; nn < 32; nn++) {
            float4 a = *(const float4*)&Ks[nn][tm];
            float4 b = *(const float4*)&Vs[nn][tn];
            float av[4] = {a.x,a.y,a.z,a.w};
            float bv[4] = {b.x,b.y,b.z,b.w};
            #pragma unroll
            for (int i = 0; i < 4; i++)
                #pragma unroll
                for (int j = 0; j < 4; j++)
                    acc[i][j] = fmaf(av[i], bv[j], acc[i][j]);
        }
        __syncthreads();
    }

    float* dst = g_kvp + (long)blockIdx.x*4096;
    #pragma unroll
    for (int i = 0; i < 4; i++)
        #pragma unroll
        for (int j = 0; j < 4; j++)
            dst[(tm+i)*64 + tn + j] = acc[i][j];
}

__global__ void kv_reduce()
{
    int idx = blockIdx.x*256 + threadIdx.x;
    int bh = idx >> 12;
    int rem = idx & 4095;
    int m = rem >> 6, d = rem & 63;
    float s = 0.f;
    #pragma unroll
    for (int sp = 0; sp < 8; sp++)
        s += g_kvp[((long)(bh*8 + sp))*4096 + rem];
    g_kvth[(long)bh*4096 + d*64 + m] = __float2half_rn(s);
}

// =====================================================================
// FUSED o = q@kv + LayerNorm -> g_xh (fp16), g_o round-trip eliminated.
//   Block: batch b, 32 seq rows. smem: 16 q-tiles (32x64) + 16 kvT (64x64)
//   Warp w computes heads 2w, 2w+1 (acc = 32 rows x 128 cols fp32).
//   LN stats: register partials -> shfl -> smem tree over full 1024 row.
// =====================================================================
#define FL_Q    0          // 65536 B : 16 x (32x64 half, 128B rows)
#define FL_B    65536      // 131072 B: 16 x (64x64 half, 128B rows)
#define FL_G    196608     // gamma fp32 4096 B
#define FL_BE   200704     // beta  fp32 4096 B
#define FL_PS   204800     // psum [8][32] fp32
#define FL_PQ   205824     // psq  [8][32] fp32
#define FL_MU   206848     // [32] fp32
#define FL_INV  206976     // [32] fp32
#define FUSE_SMEM 207104
#define STG_W   1040       // stage row stride in halves (pad vs bank conflicts)

__global__ __launch_bounds__(256, 1)
void o_ln_fused(const float* __restrict__ gamma, const float* __restrict__ beta)
{
    extern __shared__ char smem[];
    const uint32_t sb = smem_u32(smem);
    const int tid = threadIdx.x;
    const int lane = tid & 31, wid = tid >> 5;
    const int b = blockIdx.x >> 7;
    const int n0 = (blockIdx.x & 127) * 32;

    // gamma/beta to smem
    {
        float4 g4 = ((const float4*)gamma)[tid];
        float4 b4 = ((const float4*)beta)[tid];
        *(float4*)(smem + FL_G  + tid*16) = g4;
        *(float4*)(smem + FL_BE + tid*16) = b4;
    }

    // q tiles: 16 heads x 32 rows x 8 chunks
    #pragma unroll
    for (int i = 0; i < 16; i++) {
        int cid = tid + i*256;
        int h = cid >> 8;
        int rr = (cid >> 3) & 31;
        int c16 = cid & 7;
        uint32_t off = rr*128 + c16*16;
        uint32_t sw = off ^ ((off >> 3) & 0x70);
        cpa16(sb + FL_Q + h*4096 + sw,
              g_qh + (((long)(b*16 + h))*SEQ + n0 + rr)*DHEAD + c16*8);
    }
    // kvT tiles: 16 heads x 64 rows x 8 chunks
    #pragma unroll
    for (int i = 0; i < 32; i++) {
        int cid = tid + i*256;
        int h = cid >> 9;
        int rr = (cid >> 3) & 63;
        int c16 = cid & 7;
        uint32_t off = rr*128 + c16*16;
        uint32_t sw = off ^ ((off >> 3) & 0x70);
        cpa16(sb + FL_B + h*8192 + sw,
              g_kvth + ((long)(b*16 + h))*4096 + rr*64 + c16*8);
    }
    CP_COMMIT(); CP_WAIT(0);
    __syncthreads();

    const int ra  = lane & 15;
    const int kba = ((lane >> 4) & 1) * 16;
    const int nnb = (lane & 7) + ((lane >> 4) & 1)*8;
    const int kbb = ((lane >> 3) & 1) * 16;

    float acc[2][2][8][4];      // [head_local][mf][nf][c]
    #pragma unroll
    for (int a = 0; a < 2; a++)
        #pragma unroll
        for (int m = 0; m < 2; m++)
            #pragma unroll
            for (int n = 0; n < 8; n++)
                #pragma unroll
                for (int d = 0; d < 4; d++) acc[a][m][n][d] = 0.f;

    #pragma unroll
    for (int hl = 0; hl < 2; hl++) {
        const int h = wid*2 + hl;
        const uint32_t qa = sb + FL_Q + h*4096;
        const uint32_t ba = sb + FL_B + h*8192;
        #pragma unroll
        for (int k16 = 0; k16 < 4; k16++) {
            uint32_t af[2][4], bfr[4][4];
            #pragma unroll
            for (int mf = 0; mf < 2; mf++) {
                uint32_t off = (uint32_t)(mf*16 + ra)*128 + k16*32 + kba;
                uint32_t sw = off ^ ((off >> 3) & 0x70);
                ldm_x4(qa + sw, af[mf]);
            }
            #pragma unroll
            for (int np = 0; np < 4; np++) {
                uint32_t off = (uint32_t)(np*16 + nnb)*128 + k16*32 + kbb;
                uint32_t sw = off ^ ((off >> 3) & 0x70);
                ldm_x4(ba + sw, bfr[np]);
            }
            #pragma unroll
            for (int mf = 0; mf < 2; mf++)
                #pragma unroll
                for (int nf = 0; nf < 8; nf++)
                    mma16816h(acc[hl][mf][nf], af[mf], &bfr[nf >> 1][(nf & 1)*2]);
        }
    }

    // ---- LN partial sums (4 rows per lane: r0, r0+8, r0+16, r0+24) ----
    float rs[4] = {0.f,0.f,0.f,0.f}, rq[4] = {0.f,0.f,0.f,0.f};
    #pragma unroll
    for (int hl = 0; hl < 2; hl++)
        #pragma unroll
        for (int nf = 0; nf < 8; nf++) {
            float a0 = acc[hl][0][nf][0], a1 = acc[hl][0][nf][1];
            float a2 = acc[hl][0][nf][2], a3 = acc[hl][0][nf][3];
            float c0 = acc[hl][1][nf][0], c1 = acc[hl][1][nf][1];
            float c2 = acc[hl][1][nf][2], c3 = acc[hl][1][nf][3];
            rs[0] += a0 + a1;  rq[0] += a0*a0 + a1*a1;
            rs[1] += a2 + a3;  rq[1] += a2*a2 + a3*a3;
            rs[2] += c0 + c1;  rq[2] += c0*c0 + c1*c1;
            rs[3] += c2 + c3;  rq[3] += c2*c2 + c3*c3;
        }
    #pragma unroll
    for (int o = 1; o < 4; o <<= 1) {
        #pragma unroll
        for (int i = 0; i < 4; i++) {
            rs[i] += __shfl_xor_sync(0xffffffffu, rs[i], o);
            rq[i] += __shfl_xor_sync(0xffffffffu, rq[i], o);
        }
    }
    float* ps = (float*)(smem + FL_PS) + wid*32;
    float* pq = (float*)(smem + FL_PQ) + wid*32;
    if ((lane & 3) == 0) {
        int r0 = lane >> 2;
        ps[r0]    = rs[0];  pq[r0]    = rq[0];
        ps[r0+8]  = rs[1];  pq[r0+8]  = rq[1];
        ps[r0+16] = rs[2];  pq[r0+16] = rq[2];
        ps[r0+24] = rs[3];  pq[r0+24] = rq[3];
    }
    __syncthreads();
    if (tid < 32) {
        float s = 0.f, q = 0.f;
        #pragma unroll
        for (int w = 0; w < 8; w++) {
            s += ((const float*)(smem + FL_PS))[w*32 + tid];
            q += ((const float*)(smem + FL_PQ))[w*32 + tid];
        }
        float mu = s * (1.f/INNER);
        float var = q * (1.f/INNER) - mu*mu;
        ((float*)(smem + FL_MU))[tid]  = mu;
        ((float*)(smem + FL_INV))[tid] = rsqrtf(fmaxf(var, 0.f) + LN_EPS);
    }
    __syncthreads();

    // ---- normalize + stage fp16 (reuse q/kvT region; MMAs are done) ----
    __half* stage = (__half*)smem;                 // [32][STG_W]
    const float* muv = (const float*)(smem + FL_MU);
    const float* ivv = (const float*)(smem + FL_INV);
    const float* gam = (const float*)(smem + FL_G);
    const float* bet = (const float*)(smem + FL_BE);
    #pragma unroll
    for (int hl = 0; hl < 2; hl++) {
        const int h = wid*2 + hl;
        #pragma unroll
        for (int mf = 0; mf < 2; mf++) {
            int r0 = mf*16 + (lane >> 2);
            float mu0 = muv[r0],   iv0 = ivv[r0];
            float mu1 = muv[r0+8], iv1 = ivv[r0+8];
            #pragma unroll
            for (int nf = 0; nf < 8; nf++) {
                int gc = h*64 + nf*8 + (lane & 3)*2;
                float g0 = gam[gc], g1 = gam[gc+1];
                float b0 = bet[gc], b1 = bet[gc+1];
                const float* a = acc[hl][mf][nf];
                __half2 p0 = __halves2half2(
                    __float2half_rn((a[0]-mu0)*iv0*g0 + b0),
                    __float2half_rn((a[1]-mu0)*iv0*g1 + b1));
                __half2 p1 = __halves2half2(
                    __float2half_rn((a[2]-mu1)*iv1*g0 + b0),
                    __float2half_rn((a[3]-mu1)*iv1*g1 + b1));
                *(__half2*)(stage + r0*STG_W + gc)     = p0;
                *(__half2*)(stage + (r0+8)*STG_W + gc) = p1;
            }
        }
    }
    __syncthreads();

    // ---- coalesced copy out: 32 rows x 1024 halves ----
    #pragma unroll
    for (int i = 0; i < 16; i++) {
        int idx = tid + i*256;
        int row = idx >> 7, c = idx & 127;       // 128 uint4 per row
        uint4 v = *(const uint4*)(stage + row*STG_W + c*8);
        *(uint4*)(g_xh + ((long)(b*SEQ + n0 + row))*INNER + c*8) = v;
    }
}

// =====================================================================
// launcher
// =====================================================================
extern "C" void kernel_launch(void* const* d_in, const int* in_sizes, int n_in,
                              void* d_out, int out_size)
{
    const float* x     = (const float*)d_in[0];
    const float* w_qkv = (const float*)d_in[1];
    const float* gamma = (const float*)d_in[2];
    const float* beta  = (const float*)d_in[3];
    const float* w_out = (const float*)d_in[4];
    const float* b_out = (const float*)d_in[5];
    float* out = (float*)d_out;

    cudaFuncSetAttribute(mma_gemm, cudaFuncAttributeMaxDynamicSharedMemorySize, GEMM_SMEM);
    cudaFuncSetAttribute(o_ln_fused, cudaFuncAttributeMaxDynamicSharedMemorySize, FUSE_SMEM);

    // 0: all conversions in one launch
    cvt_all<<<NBX + NB1 + NB2, 256>>>(x, w_qkv, w_out);

    // 1: qkv = x @ w_qkv + relu -> q/k/v fp16
    mma_gemm<<<dim3(QKVN/128, MROWS/128), 256, GEMM_SMEM>>>(nullptr, nullptr, 0);
    // 2-3: kv = relu(k)^T v -> kv^T fp16
    kv_partial<<<512, 256>>>();
    kv_reduce<<<1024, 256>>>();
    // 4: fused o = q@kv + LayerNorm -> g_xh fp16
    o_ln_fused<<<512, 256, FUSE_SMEM>>>(gamma, beta);
    // 5: out = LN(o) @ w_out + b_out
    mma_gemm<<<dim3(DIM/128, MROWS/128), 256, GEMM_SMEM>>>(b_out, out, 1);
}

// round 15
// speedup vs baseline: 1.0671x; 1.0066x over previous
#include <cuda_runtime.h>
#include <cuda_fp16.h>
#include <cstdint>

// ---------------- problem constants ----------------
#define BATCH 4
#define SEQ   4096
#define DIM   1024
#define HEADS 16
#define DHEAD 64
#define INNER 1024
#define MROWS (BATCH*SEQ)   // 16384
#define QKVN  (3*INNER)     // 3072
#define LN_EPS 1e-5f

// ---------------- scratch (device globals; no allocs allowed) ----------------
__device__ float g_kvp[64*8*64*64];            // kv split partials (fp32)

// fp16 operand storage
__device__ __half g_xh[MROWS*DIM];             // A of GEMM1 (x) and GEMM2 (LN out)
__device__ __half g_w1h[QKVN*DIM];             // w_qkv^T [N][K]
__device__ __half g_w2h[DIM*DIM];              // w_out^T [N][K]
__device__ __half g_qh[BATCH*HEADS*SEQ*DHEAD];
__device__ __half g_kh[BATCH*HEADS*SEQ*DHEAD];
__device__ __half g_vh[BATCH*HEADS*SEQ*DHEAD];
__device__ __half g_kvth[64*64*64];            // kv^T  [bh][e][d]

// =====================================================================
// helpers
// =====================================================================
__device__ __forceinline__ uint32_t smem_u32(const void* p) {
    uint32_t a;
    asm("{ .reg .u64 t; cvta.to.shared.u64 t, %1; cvt.u32.u64 %0, t; }"
        : "=r"(a) : "l"(p));
    return a;
}

__device__ __forceinline__ void cpa16(uint32_t s, const void* g) {
    asm volatile("cp.async.cg.shared.global [%0], [%1], 16;"
                 :: "r"(s), "l"(__cvta_generic_to_global(g)) : "memory");
}
#define CP_COMMIT() asm volatile("cp.async.commit_group;" ::: "memory")
#define CP_WAIT(n)  asm volatile("cp.async.wait_group %0;" :: "n"(n) : "memory")

__device__ __forceinline__ void ldm_x4(uint32_t addr, uint32_t* r) {
    asm volatile("ldmatrix.sync.aligned.m8n8.x4.shared.b16 {%0,%1,%2,%3}, [%4];"
        : "=r"(r[0]), "=r"(r[1]), "=r"(r[2]), "=r"(r[3]) : "r"(addr));
}

__device__ __forceinline__ void mma16816h(float* d, const uint32_t* a, const uint32_t* b) {
    asm volatile("mma.sync.aligned.m16n8k16.row.col.f32.f16.f16.f32 "
        "{%0,%1,%2,%3}, {%4,%5,%6,%7}, {%8,%9}, {%0,%1,%2,%3};"
        : "+f"(d[0]), "+f"(d[1]), "+f"(d[2]), "+f"(d[3])
        : "r"(a[0]), "r"(a[1]), "r"(a[2]), "r"(a[3]), "r"(b[0]), "r"(b[1]));
}

__device__ __forceinline__ uint32_t pack2h(__half a, __half b) {
    __half2 t = __halves2half2(a, b);
    return *reinterpret_cast<uint32_t*>(&t);
}

// packed fp32x2 FMA (sm_100+ base feature; 2 FMAs per issue slot)
__device__ __forceinline__ unsigned long long packf2(float lo, float hi) {
    unsigned long long r;
    asm("mov.b64 %0, {%1, %2};" : "=l"(r) : "f"(lo), "f"(hi));
    return r;
}
__device__ __forceinline__ void unpackf2(unsigned long long v, float& lo, float& hi) {
    asm("mov.b64 {%0, %1}, %2;" : "=f"(lo), "=f"(hi) : "l"(v));
}
#define FMA2(d, a, b) \
    asm("fma.rn.f32x2 %0, %1, %2, %0;" : "+l"(d) : "l"(a), "l"(b))

// =====================================================================
// fused conversion kernel: one launch covers x, w_qkv^T, w_out^T
// =====================================================================
#define NBX (MROWS*DIM/1024)   // 16384
#define NB1 (96*32)            // 3072
#define NB2 (32*32)            // 1024

__global__ __launch_bounds__(256)
void cvt_all(const float* __restrict__ x,
             const float* __restrict__ w1,
             const float* __restrict__ w2)
{
    const int tid = threadIdx.x;
    int blk = blockIdx.x;

    if (blk < NBX) {
        long i = (long)blk*256 + tid;
        float4 v = ((const float4*)x)[i];
        ((uint2*)g_xh)[i] = make_uint2(
            pack2h(__float2half_rn(v.x), __float2half_rn(v.y)),
            pack2h(__float2half_rn(v.z), __float2half_rn(v.w)));
        return;
    }
    blk -= NBX;

    const float* in;
    __half* hi;
    int N, bx;
    if (blk < NB1) { in = w1; hi = g_w1h; N = QKVN; bx = blk; }
    else           { in = w2; hi = g_w2h; N = DIM;  bx = blk - NB1; }

    __shared__ float t[32][33];
    const int nblk_n = N / 32;
    const int n0 = (bx % nblk_n) * 32;
    const int k0 = (bx / nblk_n) * 32;

    #pragma unroll
    for (int i = 0; i < 4; i++) {
        int r = (tid >> 5) + i*8, c = tid & 31;
        t[r][c] = in[(long)(k0+r)*N + n0 + c];
    }
    __syncthreads();
    #pragma unroll
    for (int i = 0; i < 4; i++) {
        int a = (tid >> 5) + i*8;
        int b = tid & 31;
        hi[(long)(n0+a)*DIM + k0 + b] = __float2half_rn(t[b][a]);
    }
}

// =====================================================================
// fp16 mma.sync GEMM — R12 configuration (measured best):
//   CTA 128x128, 8 warps, warp 64x32, K-chunk 64, 3-stage, 2 CTAs/SM
// =====================================================================
#define ST_A 0
#define ST_B 16384
#define ST_SZ 32768
#define GEMM_SMEM (3*ST_SZ)

__global__ __launch_bounds__(256, 2)
void mma_gemm(const float* __restrict__ bias, float* __restrict__ Cout, int mode)
{
    extern __shared__ char smem[];
    const uint32_t sb = smem_u32(smem);
    const int tid  = threadIdx.x;
    const int lane = tid & 31, wid = tid >> 5;
    const int wm = wid >> 2, wn = wid & 3;
    const int m0 = blockIdx.y * 128;
    const int n0 = blockIdx.x * 128;

    const __half* Ah = g_xh;
    const __half* Bh = mode ? g_w2h : g_w1h;

    auto issue = [&](int chunk, int buf) {
        const uint32_t so = sb + buf*ST_SZ;
        const int kofs = chunk * 64;
        #pragma unroll
        for (int i = 0; i < 4; i++) {
            int cid = tid + i*256;
            int row = cid >> 3, c16 = cid & 7;
            uint32_t off = row*128 + c16*16;
            uint32_t sw = off ^ ((off >> 3) & 0x70);
            cpa16(so + ST_A + sw, Ah + (long)(m0 + row)*DIM + kofs + c16*8);
        }
        #pragma unroll
        for (int i = 0; i < 4; i++) {
            int cid = tid + i*256;
            int row = cid >> 3, c16 = cid & 7;
            uint32_t off = row*128 + c16*16;
            uint32_t sw = off ^ ((off >> 3) & 0x70);
            cpa16(so + ST_B + sw, Bh + (long)(n0 + row)*DIM + kofs + c16*8);
        }
        CP_COMMIT();
    };

    const int ra  = lane & 15;
    const int kba = ((lane >> 4) & 1) * 16;
    const int nnb = (lane & 7) + ((lane >> 4) & 1)*8;
    const int kbb = ((lane >> 3) & 1) * 16;

    float acc[4][4][4];
    #pragma unroll
    for (int a = 0; a < 4; a++)
        #pragma unroll
        for (int b = 0; b < 4; b++)
            #pragma unroll
            for (int d = 0; d < 4; d++) acc[a][b][d] = 0.f;

    issue(0, 0); issue(1, 1);

    int buf = 0, nbuf = 2;
    #pragma unroll 1
    for (int c = 0; c < 16; c++) {
        if (c < 15) { CP_WAIT(1); } else { CP_WAIT(0); }
        __syncthreads();
        if (c + 2 < 16) issue(c + 2, nbuf);

        const uint32_t so = sb + buf*ST_SZ;

        #pragma unroll
        for (int k16 = 0; k16 < 4; k16++) {
            uint32_t ah[4][4], bf2[2][4];
            {
                const int ka = k16*32 + kba;
                #pragma unroll
                for (int mf = 0; mf < 4; mf++) {
                    uint32_t off = (uint32_t)(wm*64 + mf*16 + ra)*128 + ka;
                    uint32_t sw = off ^ ((off >> 3) & 0x70);
                    ldm_x4(so + ST_A + sw, ah[mf]);
                }
            }
            {
                const int kb = k16*32 + kbb;
                #pragma unroll
                for (int np = 0; np < 2; np++) {
                    uint32_t off = (uint32_t)(wn*32 + np*16 + nnb)*128 + kb;
                    uint32_t sw = off ^ ((off >> 3) & 0x70);
                    ldm_x4(so + ST_B + sw, bf2[np]);
                }
            }
            #pragma unroll
            for (int mf = 0; mf < 4; mf++)
                #pragma unroll
                for (int nf = 0; nf < 4; nf++)
                    mma16816h(acc[mf][nf], ah[mf], &bf2[nf >> 1][(nf & 1)*2]);
        }
        buf = (buf == 2) ? 0 : buf + 1;
        nbuf = (nbuf == 2) ? 0 : nbuf + 1;
    }
    __syncthreads();

    float* stg = (float*)smem;                      // [128][132]
    #pragma unroll
    for (int mf = 0; mf < 4; mf++)
        #pragma unroll
        for (int nf = 0; nf < 4; nf++) {
            int row = wm*64 + mf*16 + (lane >> 2);
            int col = wn*32 + nf*8 + (lane & 3)*2;
            stg[row*132 + col]       = acc[mf][nf][0];
            stg[row*132 + col + 1]   = acc[mf][nf][1];
            stg[(row+8)*132 + col]   = acc[mf][nf][2];
            stg[(row+8)*132 + col+1] = acc[mf][nf][3];
        }
    __syncthreads();

    #pragma unroll 1
    for (int i = 0; i < 16; i++) {
        int slot = tid + i*256;
        int row = slot >> 5, c4 = slot & 31;
        float4 v = *(const float4*)&stg[row*132 + c4*4];
        int gm = m0 + row;
        int gn = n0 + c4*4;
        if (mode == 0) {
            int part = gn >> 10;
            int inner = gn & 1023;
            int h = inner >> 6, d = inner & 63;
            int b = gm >> 12, s = gm & 4095;
            long dst = (((long)(b*16 + h))*4096 + s)*64 + d;
            if (part != 2) {
                v.x = fmaxf(v.x, 0.f); v.y = fmaxf(v.y, 0.f);
                v.z = fmaxf(v.z, 0.f); v.w = fmaxf(v.w, 0.f);
            }
            uint2 uh = make_uint2(
                pack2h(__float2half_rn(v.x), __float2half_rn(v.y)),
                pack2h(__float2half_rn(v.z), __float2half_rn(v.w)));
            if (part == 0)      *(uint2*)(g_qh+dst) = uh;
            else if (part == 1) *(uint2*)(g_kh+dst) = uh;
            else                *(uint2*)(g_vh+dst) = uh;
        } else {
            float4 bs = *(const float4*)(bias + gn);
            v.x += bs.x; v.y += bs.y; v.z += bs.z; v.w += bs.w;
            *(float4*)(Cout + (long)gm*DIM + gn) = v;
        }
    }
}

// =====================================================================
// kv partials: packed f32x2 FMA (2 fp32 FMA per issue slot)
// =====================================================================
__global__ __launch_bounds__(256)
void kv_partial()
{
    const int bh = blockIdx.x >> 3;
    const int split = blockIdx.x & 7;
    __shared__ float Ks[32][64];
    __shared__ float Vs[32][64];

    const int tid = threadIdx.x;
    const int tm = (tid >> 4) << 2;
    const int tn = (tid & 15) << 2;

    unsigned long long accp[4][2];
    #pragma unroll
    for (int i = 0; i < 4; i++) { accp[i][0] = 0ull; accp[i][1] = 0ull; }

    const long base = ((long)bh*SEQ + split*512)*DHEAD;

    for (int n0 = 0; n0 < 512; n0 += 32) {
        #pragma unroll
        for (int r = 0; r < 2; r++) {
            int idx = tid + r*256;
            int row = idx >> 4;
            int col = (idx & 15) << 2;
            long a = base + (long)(n0+row)*DHEAD + col;
            uint2 uk = *(const uint2*)(g_kh+a);
            uint2 uv = *(const uint2*)(g_vh+a);
            __half2 k0 = *reinterpret_cast<__half2*>(&uk.x);
            __half2 k1 = *reinterpret_cast<__half2*>(&uk.y);
            __half2 v0 = *reinterpret_cast<__half2*>(&uv.x);
            __half2 v1 = *reinterpret_cast<__half2*>(&uv.y);
            Ks[row][col+0] = __low2float(k0);  Ks[row][col+1] = __high2float(k0);
            Ks[row][col+2] = __low2float(k1);  Ks[row][col+3] = __high2float(k1);
            Vs[row][col+0] = __low2float(v0);  Vs[row][col+1] = __high2float(v0);
            Vs[row][col+2] = __low2float(v1);  Vs[row][col+3] = __high2float(v1);
        }
        __syncthreads();
        #pragma unroll
        for (int nn = 0; nn < 32; nn++) {
            float4 a = *(const float4*)&Ks[nn][tm];
            float4 b = *(const float4*)&Vs[nn][tn];
            unsigned long long b0 = packf2(b.x, b.y);
            unsigned long long b1 = packf2(b.z, b.w);
            unsigned long long a0 = packf2(a.x, a.x);
            unsigned long long a1 = packf2(a.y, a.y);
            unsigned long long a2 = packf2(a.z, a.z);
            unsigned long long a3 = packf2(a.w, a.w);
            FMA2(accp[0][0], a0, b0);  FMA2(accp[0][1], a0, b1);
            FMA2(accp[1][0], a1, b0);  FMA2(accp[1][1], a1, b1);
            FMA2(accp[2][0], a2, b0);  FMA2(accp[2][1], a2, b1);
            FMA2(accp[3][0], a3, b0);  FMA2(accp[3][1], a3, b1);
        }
        __syncthreads();
    }

    float* dst = g_kvp + (long)blockIdx.x*4096;
    #pragma unroll
    for (int i = 0; i < 4; i++) {
        float c0, c1, c2, c3;
        unpackf2(accp[i][0], c0, c1);
        unpackf2(accp[i][1], c2, c3);
        dst[(tm+i)*64 + tn + 0] = c0;
        dst[(tm+i)*64 + tn + 1] = c1;
        dst[(tm+i)*64 + tn + 2] = c2;
        dst[(tm+i)*64 + tn + 3] = c3;
    }
}

__global__ void kv_reduce()
{
    int idx = blockIdx.x*256 + threadIdx.x;
    int bh = idx >> 12;
    int rem = idx & 4095;
    int m = rem >> 6, d = rem & 63;
    float s = 0.f;
    #pragma unroll
    for (int sp = 0; sp < 8; sp++)
        s += g_kvp[((long)(bh*8 + sp))*4096 + rem];
    g_kvth[(long)bh*4096 + d*64 + m] = __float2half_rn(s);
}

// =====================================================================
// FUSED o = q@kv + LayerNorm -> g_xh (fp16)  (unchanged from R14)
// =====================================================================
#define FL_Q    0
#define FL_B    65536
#define FL_G    196608
#define FL_BE   200704
#define FL_PS   204800
#define FL_PQ   205824
#define FL_MU   206848
#define FL_INV  206976
#define FUSE_SMEM 207104
#define STG_W   1040

__global__ __launch_bounds__(256, 1)
void o_ln_fused(const float* __restrict__ gamma, const float* __restrict__ beta)
{
    extern __shared__ char smem[];
    const uint32_t sb = smem_u32(smem);
    const int tid = threadIdx.x;
    const int lane = tid & 31, wid = tid >> 5;
    const int b = blockIdx.x >> 7;
    const int n0 = (blockIdx.x & 127) * 32;

    {
        float4 g4 = ((const float4*)gamma)[tid];
        float4 b4 = ((const float4*)beta)[tid];
        *(float4*)(smem + FL_G  + tid*16) = g4;
        *(float4*)(smem + FL_BE + tid*16) = b4;
    }

    #pragma unroll
    for (int i = 0; i < 16; i++) {
        int cid = tid + i*256;
        int h = cid >> 8;
        int rr = (cid >> 3) & 31;
        int c16 = cid & 7;
        uint32_t off = rr*128 + c16*16;
        uint32_t sw = off ^ ((off >> 3) & 0x70);
        cpa16(sb + FL_Q + h*4096 + sw,
              g_qh + (((long)(b*16 + h))*SEQ + n0 + rr)*DHEAD + c16*8);
    }
    #pragma unroll
    for (int i = 0; i < 32; i++) {
        int cid = tid + i*256;
        int h = cid >> 9;
        int rr = (cid >> 3) & 63;
        int c16 = cid & 7;
        uint32_t off = rr*128 + c16*16;
        uint32_t sw = off ^ ((off >> 3) & 0x70);
        cpa16(sb + FL_B + h*8192 + sw,
              g_kvth + ((long)(b*16 + h))*4096 + rr*64 + c16*8);
    }
    CP_COMMIT(); CP_WAIT(0);
    __syncthreads();

    const int ra  = lane & 15;
    const int kba = ((lane >> 4) & 1) * 16;
    const int nnb = (lane & 7) + ((lane >> 4) & 1)*8;
    const int kbb = ((lane >> 3) & 1) * 16;

    float acc[2][2][8][4];
    #pragma unroll
    for (int a = 0; a < 2; a++)
        #pragma unroll
        for (int m = 0; m < 2; m++)
            #pragma unroll
            for (int n = 0; n < 8; n++)
                #pragma unroll
                for (int d = 0; d < 4; d++) acc[a][m][n][d] = 0.f;

    #pragma unroll
    for (int hl = 0; hl < 2; hl++) {
        const int h = wid*2 + hl;
        const uint32_t qa = sb + FL_Q + h*4096;
        const uint32_t ba = sb + FL_B + h*8192;
        #pragma unroll
        for (int k16 = 0; k16 < 4; k16++) {
            uint32_t af[2][4], bfr[4][4];
            #pragma unroll
            for (int mf = 0; mf < 2; mf++) {
                uint32_t off = (uint32_t)(mf*16 + ra)*128 + k16*32 + kba;
                uint32_t sw = off ^ ((off >> 3) & 0x70);
                ldm_x4(qa + sw, af[mf]);
            }
            #pragma unroll
            for (int np = 0; np < 4; np++) {
                uint32_t off = (uint32_t)(np*16 + nnb)*128 + k16*32 + kbb;
                uint32_t sw = off ^ ((off >> 3) & 0x70);
                ldm_x4(ba + sw, bfr[np]);
            }
            #pragma unroll
            for (int mf = 0; mf < 2; mf++)
                #pragma unroll
                for (int nf = 0; nf < 8; nf++)
                    mma16816h(acc[hl][mf][nf], af[mf], &bfr[nf >> 1][(nf & 1)*2]);
        }
    }

    float rs[4] = {0.f,0.f,0.f,0.f}, rq[4] = {0.f,0.f,0.f,0.f};
    #pragma unroll
    for (int hl = 0; hl < 2; hl++)
        #pragma unroll
        for (int nf = 0; nf < 8; nf++) {
            float a0 = acc[hl][0][nf][0], a1 = acc[hl][0][nf][1];
            float a2 = acc[hl][0][nf][2], a3 = acc[hl][0][nf][3];
            float c0 = acc[hl][1][nf][0], c1 = acc[hl][1][nf][1];
            float c2 = acc[hl][1][nf][2], c3 = acc[hl][1][nf][3];
            rs[0] += a0 + a1;  rq[0] += a0*a0 + a1*a1;
            rs[1] += a2 + a3;  rq[1] += a2*a2 + a3*a3;
            rs[2] += c0 + c1;  rq[2] += c0*c0 + c1*c1;
            rs[3] += c2 + c3;  rq[3] += c2*c2 + c3*c3;
        }
    #pragma unroll
    for (int o = 1; o < 4; o <<= 1) {
        #pragma unroll
        for (int i = 0; i < 4; i++) {
            rs[i] += __shfl_xor_sync(0xffffffffu, rs[i], o);
            rq[i] += __shfl_xor_sync(0xffffffffu, rq[i], o);
        }
    }
    float* ps = (float*)(smem + FL_PS) + wid*32;
    float* pq = (float*)(smem + FL_PQ) + wid*32;
    if ((lane & 3) == 0) {
        int r0 = lane >> 2;
        ps[r0]    = rs[0];  pq[r0]    = rq[0];
        ps[r0+8]  = rs[1];  pq[r0+8]  = rq[1];
        ps[r0+16] = rs[2];  pq[r0+16] = rq[2];
        ps[r0+24] = rs[3];  pq[r0+24] = rq[3];
    }
    __syncthreads();
    if (tid < 32) {
        float s = 0.f, q = 0.f;
        #pragma unroll
        for (int w = 0; w < 8; w++) {
            s += ((const float*)(smem + FL_PS))[w*32 + tid];
            q += ((const float*)(smem + FL_PQ))[w*32 + tid];
        }
        float mu = s * (1.f/INNER);
        float var = q * (1.f/INNER) - mu*mu;
        ((float*)(smem + FL_MU))[tid]  = mu;
        ((float*)(smem + FL_INV))[tid] = rsqrtf(fmaxf(var, 0.f) + LN_EPS);
    }
    __syncthreads();

    __half* stage = (__half*)smem;
    const float* muv = (const float*)(smem + FL_MU);
    const float* ivv = (const float*)(smem + FL_INV);
    const float* gam = (const float*)(smem + FL_G);
    const float* bet = (const float*)(smem + FL_BE);
    #pragma unroll
    for (int hl = 0; hl < 2; hl++) {
        const int h = wid*2 + hl;
        #pragma unroll
        for (int mf = 0; mf < 2; mf++) {
            int r0 = mf*16 + (lane >> 2);
            float mu0 = muv[r0],   iv0 = ivv[r0];
            float mu1 = muv[r0+8], iv1 = ivv[r0+8];
            #pragma unroll
            for (int nf = 0; nf < 8; nf++) {
                int gc = h*64 + nf*8 + (lane & 3)*2;
                float g0 = gam[gc], g1 = gam[gc+1];
                float b0 = bet[gc], b1 = bet[gc+1];
                const float* a = acc[hl][mf][nf];
                __half2 p0 = __halves2half2(
                    __float2half_rn((a[0]-mu0)*iv0*g0 + b0),
                    __float2half_rn((a[1]-mu0)*iv0*g1 + b1));
                __half2 p1 = __halves2half2(
                    __float2half_rn((a[2]-mu1)*iv1*g0 + b0),
                    __float2half_rn((a[3]-mu1)*iv1*g1 + b1));
                *(__half2*)(stage + r0*STG_W + gc)     = p0;
                *(__half2*)(stage + (r0+8)*STG_W + gc) = p1;
            }
        }
    }
    __syncthreads();

    #pragma unroll
    for (int i = 0; i < 16; i++) {
        int idx = tid + i*256;
        int row = idx >> 7, c = idx & 127;
        uint4 v = *(const uint4*)(stage + row*STG_W + c*8);
        *(uint4*)(g_xh + ((long)(b*SEQ + n0 + row))*INNER + c*8) = v;
    }
}

// =====================================================================
// launcher
// =====================================================================
extern "C" void kernel_launch(void* const* d_in, const int* in_sizes, int n_in,
                              void* d_out, int out_size)
{
    const float* x     = (const float*)d_in[0];
    const float* w_qkv = (const float*)d_in[1];
    const float* gamma = (const float*)d_in[2];
    const float* beta  = (const float*)d_in[3];
    const float* w_out = (const float*)d_in[4];
    const float* b_out = (const float*)d_in[5];
    float* out = (float*)d_out;

    cudaFuncSetAttribute(mma_gemm, cudaFuncAttributeMaxDynamicSharedMemorySize, GEMM_SMEM);
    cudaFuncSetAttribute(o_ln_fused, cudaFuncAttributeMaxDynamicSharedMemorySize, FUSE_SMEM);

    cvt_all<<<NBX + NB1 + NB2, 256>>>(x, w_qkv, w_out);

    mma_gemm<<<dim3(QKVN/128, MROWS/128), 256, GEMM_SMEM>>>(nullptr, nullptr, 0);
    kv_partial<<<512, 256>>>();
    kv_reduce<<<1024, 256>>>();
    o_ln_fused<<<512, 256, FUSE_SMEM>>>(gamma, beta);
    mma_gemm<<<dim3(DIM/128, MROWS/128), 256, GEMM_SMEM>>>(b_out, out, 1);
}

// round 16
// speedup vs baseline: 1.1957x; 1.1205x over previous
#include <cuda_runtime.h>
#include <cuda_fp16.h>
#include <cstdint>

// ---------------- problem constants ----------------
#define BATCH 4
#define SEQ   4096
#define DIM   1024
#define HEADS 16
#define DHEAD 64
#define INNER 1024
#define MROWS (BATCH*SEQ)   // 16384
#define QKVN  (3*INNER)     // 3072
#define LN_EPS 1e-5f

// ---------------- scratch (device globals; no allocs allowed) ----------------
__device__ float g_kvp[64*8*64*64];            // kv split partials (fp32)

// fp16 operand storage
__device__ __half g_xh[MROWS*DIM];             // A of GEMM1 (x) and GEMM2 (LN out)
__device__ __half g_w1h[QKVN*DIM];             // w_qkv^T [N][K]
__device__ __half g_w2h[DIM*DIM];              // w_out^T [N][K]
__device__ __half g_qh[BATCH*HEADS*SEQ*DHEAD];
__device__ __half g_kh[BATCH*HEADS*SEQ*DHEAD];
__device__ __half g_vh[BATCH*HEADS*SEQ*DHEAD];
__device__ __half g_kvth[64*64*64];            // kv^T  [bh][e][d]

// =====================================================================
// helpers
// =====================================================================
__device__ __forceinline__ uint32_t smem_u32(const void* p) {
    uint32_t a;
    asm("{ .reg .u64 t; cvta.to.shared.u64 t, %1; cvt.u32.u64 %0, t; }"
        : "=r"(a) : "l"(p));
    return a;
}

__device__ __forceinline__ void cpa16(uint32_t s, const void* g) {
    asm volatile("cp.async.cg.shared.global [%0], [%1], 16;"
                 :: "r"(s), "l"(__cvta_generic_to_global(g)) : "memory");
}
#define CP_COMMIT() asm volatile("cp.async.commit_group;" ::: "memory")
#define CP_WAIT(n)  asm volatile("cp.async.wait_group %0;" :: "n"(n) : "memory")

__device__ __forceinline__ void ldm_x4(uint32_t addr, uint32_t* r) {
    asm volatile("ldmatrix.sync.aligned.m8n8.x4.shared.b16 {%0,%1,%2,%3}, [%4];"
        : "=r"(r[0]), "=r"(r[1]), "=r"(r[2]), "=r"(r[3]) : "r"(addr));
}

__device__ __forceinline__ void ldm_x4_t(uint32_t addr, uint32_t* r) {
    asm volatile("ldmatrix.sync.aligned.m8n8.x4.trans.shared.b16 {%0,%1,%2,%3}, [%4];"
        : "=r"(r[0]), "=r"(r[1]), "=r"(r[2]), "=r"(r[3]) : "r"(addr));
}

__device__ __forceinline__ void mma16816h(float* d, const uint32_t* a, const uint32_t* b) {
    asm volatile("mma.sync.aligned.m16n8k16.row.col.f32.f16.f16.f32 "
        "{%0,%1,%2,%3}, {%4,%5,%6,%7}, {%8,%9}, {%0,%1,%2,%3};"
        : "+f"(d[0]), "+f"(d[1]), "+f"(d[2]), "+f"(d[3])
        : "r"(a[0]), "r"(a[1]), "r"(a[2]), "r"(a[3]), "r"(b[0]), "r"(b[1]));
}

__device__ __forceinline__ uint32_t pack2h(__half a, __half b) {
    __half2 t = __halves2half2(a, b);
    return *reinterpret_cast<uint32_t*>(&t);
}

// =====================================================================
// fused conversion kernel: one launch covers x, w_qkv^T, w_out^T
// =====================================================================
#define NBX (MROWS*DIM/1024)   // 16384
#define NB1 (96*32)            // 3072
#define NB2 (32*32)            // 1024

__global__ __launch_bounds__(256)
void cvt_all(const float* __restrict__ x,
             const float* __restrict__ w1,
             const float* __restrict__ w2)
{
    const int tid = threadIdx.x;
    int blk = blockIdx.x;

    if (blk < NBX) {
        long i = (long)blk*256 + tid;
        float4 v = ((const float4*)x)[i];
        ((uint2*)g_xh)[i] = make_uint2(
            pack2h(__float2half_rn(v.x), __float2half_rn(v.y)),
            pack2h(__float2half_rn(v.z), __float2half_rn(v.w)));
        return;
    }
    blk -= NBX;

    const float* in;
    __half* hi;
    int N, bx;
    if (blk < NB1) { in = w1; hi = g_w1h; N = QKVN; bx = blk; }
    else           { in = w2; hi = g_w2h; N = DIM;  bx = blk - NB1; }

    __shared__ float t[32][33];
    const int nblk_n = N / 32;
    const int n0 = (bx % nblk_n) * 32;
    const int k0 = (bx / nblk_n) * 32;

    #pragma unroll
    for (int i = 0; i < 4; i++) {
        int r = (tid >> 5) + i*8, c = tid & 31;
        t[r][c] = in[(long)(k0+r)*N + n0 + c];
    }
    __syncthreads();
    #pragma unroll
    for (int i = 0; i < 4; i++) {
        int a = (tid >> 5) + i*8;
        int b = tid & 31;
        hi[(long)(n0+a)*DIM + k0 + b] = __float2half_rn(t[b][a]);
    }
}

// =====================================================================
// fp16 mma.sync GEMM — R12 configuration (measured best):
//   CTA 128x128, 8 warps, warp 64x32, K-chunk 64, 3-stage, 2 CTAs/SM
// =====================================================================
#define ST_A 0
#define ST_B 16384
#define ST_SZ 32768
#define GEMM_SMEM (3*ST_SZ)

__global__ __launch_bounds__(256, 2)
void mma_gemm(const float* __restrict__ bias, float* __restrict__ Cout, int mode)
{
    extern __shared__ char smem[];
    const uint32_t sb = smem_u32(smem);
    const int tid  = threadIdx.x;
    const int lane = tid & 31, wid = tid >> 5;
    const int wm = wid >> 2, wn = wid & 3;
    const int m0 = blockIdx.y * 128;
    const int n0 = blockIdx.x * 128;

    const __half* Ah = g_xh;
    const __half* Bh = mode ? g_w2h : g_w1h;

    auto issue = [&](int chunk, int buf) {
        const uint32_t so = sb + buf*ST_SZ;
        const int kofs = chunk * 64;
        #pragma unroll
        for (int i = 0; i < 4; i++) {
            int cid = tid + i*256;
            int row = cid >> 3, c16 = cid & 7;
            uint32_t off = row*128 + c16*16;
            uint32_t sw = off ^ ((off >> 3) & 0x70);
            cpa16(so + ST_A + sw, Ah + (long)(m0 + row)*DIM + kofs + c16*8);
        }
        #pragma unroll
        for (int i = 0; i < 4; i++) {
            int cid = tid + i*256;
            int row = cid >> 3, c16 = cid & 7;
            uint32_t off = row*128 + c16*16;
            uint32_t sw = off ^ ((off >> 3) & 0x70);
            cpa16(so + ST_B + sw, Bh + (long)(n0 + row)*DIM + kofs + c16*8);
        }
        CP_COMMIT();
    };

    const int ra  = lane & 15;
    const int kba = ((lane >> 4) & 1) * 16;
    const int nnb = (lane & 7) + ((lane >> 4) & 1)*8;
    const int kbb = ((lane >> 3) & 1) * 16;

    float acc[4][4][4];
    #pragma unroll
    for (int a = 0; a < 4; a++)
        #pragma unroll
        for (int b = 0; b < 4; b++)
            #pragma unroll
            for (int d = 0; d < 4; d++) acc[a][b][d] = 0.f;

    issue(0, 0); issue(1, 1);

    int buf = 0, nbuf = 2;
    #pragma unroll 1
    for (int c = 0; c < 16; c++) {
        if (c < 15) { CP_WAIT(1); } else { CP_WAIT(0); }
        __syncthreads();
        if (c + 2 < 16) issue(c + 2, nbuf);

        const uint32_t so = sb + buf*ST_SZ;

        #pragma unroll
        for (int k16 = 0; k16 < 4; k16++) {
            uint32_t ah[4][4], bf2[2][4];
            {
                const int ka = k16*32 + kba;
                #pragma unroll
                for (int mf = 0; mf < 4; mf++) {
                    uint32_t off = (uint32_t)(wm*64 + mf*16 + ra)*128 + ka;
                    uint32_t sw = off ^ ((off >> 3) & 0x70);
                    ldm_x4(so + ST_A + sw, ah[mf]);
                }
            }
            {
                const int kb = k16*32 + kbb;
                #pragma unroll
                for (int np = 0; np < 2; np++) {
                    uint32_t off = (uint32_t)(wn*32 + np*16 + nnb)*128 + kb;
                    uint32_t sw = off ^ ((off >> 3) & 0x70);
                    ldm_x4(so + ST_B + sw, bf2[np]);
                }
            }
            #pragma unroll
            for (int mf = 0; mf < 4; mf++)
                #pragma unroll
                for (int nf = 0; nf < 4; nf++)
                    mma16816h(acc[mf][nf], ah[mf], &bf2[nf >> 1][(nf & 1)*2]);
        }
        buf = (buf == 2) ? 0 : buf + 1;
        nbuf = (nbuf == 2) ? 0 : nbuf + 1;
    }
    __syncthreads();

    float* stg = (float*)smem;                      // [128][132]
    #pragma unroll
    for (int mf = 0; mf < 4; mf++)
        #pragma unroll
        for (int nf = 0; nf < 4; nf++) {
            int row = wm*64 + mf*16 + (lane >> 2);
            int col = wn*32 + nf*8 + (lane & 3)*2;
            stg[row*132 + col]       = acc[mf][nf][0];
            stg[row*132 + col + 1]   = acc[mf][nf][1];
            stg[(row+8)*132 + col]   = acc[mf][nf][2];
            stg[(row+8)*132 + col+1] = acc[mf][nf][3];
        }
    __syncthreads();

    #pragma unroll 1
    for (int i = 0; i < 16; i++) {
        int slot = tid + i*256;
        int row = slot >> 5, c4 = slot & 31;
        float4 v = *(const float4*)&stg[row*132 + c4*4];
        int gm = m0 + row;
        int gn = n0 + c4*4;
        if (mode == 0) {
            int part = gn >> 10;
            int inner = gn & 1023;
            int h = inner >> 6, d = inner & 63;
            int b = gm >> 12, s = gm & 4095;
            long dst = (((long)(b*16 + h))*4096 + s)*64 + d;
            if (part != 2) {
                v.x = fmaxf(v.x, 0.f); v.y = fmaxf(v.y, 0.f);
                v.z = fmaxf(v.z, 0.f); v.w = fmaxf(v.w, 0.f);
            }
            uint2 uh = make_uint2(
                pack2h(__float2half_rn(v.x), __float2half_rn(v.y)),
                pack2h(__float2half_rn(v.z), __float2half_rn(v.w)));
            if (part == 0)      *(uint2*)(g_qh+dst) = uh;
            else if (part == 1) *(uint2*)(g_kh+dst) = uh;
            else                *(uint2*)(g_vh+dst) = uh;
        } else {
            float4 bs = *(const float4*)(bias + gn);
            v.x += bs.x; v.y += bs.y; v.z += bs.z; v.w += bs.w;
            *(float4*)(Cout + (long)gm*DIM + gn) = v;
        }
    }
}

// =====================================================================
// kv partials on the TENSOR pipe via ldmatrix.trans (no scalar transpose):
//   kvp[d][e] = sum_n k[n][d] * v[n][e]
//   A = k^T via ldm.trans, B = v (col-major frag) via ldm.trans.
//   Per block: 512 n-rows in 8 subtiles of 64, 2-stage cp.async.
//   8 warps = 4(m16 d-blocks) x 2(n32 e-blocks); acc 16 fp32/thread.
// =====================================================================
#define KV_K 0
#define KV_V 8192
#define KV_STAGE 16384

__global__ __launch_bounds__(256)
void kv_partial()
{
    __shared__ char sm[2*KV_STAGE];   // 32 KB
    const uint32_t sb = smem_u32(sm);
    const int bh = blockIdx.x >> 3;
    const int split = blockIdx.x & 7;
    const int tid = threadIdx.x;
    const int lane = tid & 31, wid = tid >> 5;
    const int wm4 = wid >> 1;          // 0..3  (d-block, m16)
    const int wn2 = wid & 1;           // 0..1  (e-block, n32)

    const long base = ((long)bh*SEQ + split*512)*DHEAD;

    auto issue = [&](int sub) {
        const uint32_t so = sb + (sub & 1)*KV_STAGE;
        const long nb = base + (long)(sub*64)*DHEAD;
        #pragma unroll
        for (int i = 0; i < 2; i++) {
            int cid = tid + i*256;            // 512 chunks: 64 rows x 8
            int row = cid >> 3, c16 = cid & 7;
            uint32_t off = row*128 + c16*16;
            uint32_t sw = off ^ ((off >> 3) & 0x70);
            cpa16(so + KV_K + sw, g_kh + nb + (long)row*DHEAD + c16*8);
            cpa16(so + KV_V + sw, g_vh + nb + (long)row*DHEAD + c16*8);
        }
        CP_COMMIT();
    };

    float acc[4][4];
    #pragma unroll
    for (int i = 0; i < 4; i++)
        #pragma unroll
        for (int j = 0; j < 4; j++) acc[i][j] = 0.f;

    issue(0);

    #pragma unroll 1
    for (int sub = 0; sub < 8; sub++) {
        if (sub + 1 < 8) { issue(sub + 1); CP_WAIT(1); }
        else             { CP_WAIT(0); }
        __syncthreads();

        const uint32_t so = sb + (sub & 1)*KV_STAGE;

        #pragma unroll
        for (int k16 = 0; k16 < 4; k16++) {
            uint32_t af[4];
            {
                // A = k^T: trans load from S[k][d]; quadrant map:
                // row = k-base + ((lane>>4)&1)*8 + (lane&7); col = m0*2 + ((lane>>3)&1)*16
                int row = k16*16 + ((lane >> 4) & 1)*8 + (lane & 7);
                int colB = wm4*32 + ((lane >> 3) & 1)*16;
                uint32_t off = (uint32_t)row*128 + colB;
                uint32_t sw = off ^ ((off >> 3) & 0x70);
                ldm_x4_t(so + KV_K + sw, af);
            }
            uint32_t bf[2][4];
            #pragma unroll
            for (int np = 0; np < 2; np++) {
                // B = v (col-major frag): trans load from S[k][e]; quadrant map:
                // row = k-base + ((lane>>3)&1)*8 + (lane&7); col = n0*2 + ((lane>>4)&1)*16
                int row = k16*16 + ((lane >> 3) & 1)*8 + (lane & 7);
                int colB = wn2*64 + np*32 + ((lane >> 4) & 1)*16;
                uint32_t off = (uint32_t)row*128 + colB;
                uint32_t sw = off ^ ((off >> 3) & 0x70);
                ldm_x4_t(so + KV_V + sw, bf[np]);
            }
            #pragma unroll
            for (int nf = 0; nf < 4; nf++)
                mma16816h(acc[nf], af, &bf[nf >> 1][(nf & 1)*2]);
        }
        __syncthreads();
    }

    float* dst = g_kvp + (long)blockIdx.x*4096;
    #pragma unroll
    for (int nf = 0; nf < 4; nf++) {
        int row = wm4*16 + (lane >> 2);
        int col = wn2*32 + nf*8 + (lane & 3)*2;
        dst[row*64 + col]         = acc[nf][0];
        dst[row*64 + col + 1]     = acc[nf][1];
        dst[(row+8)*64 + col]     = acc[nf][2];
        dst[(row+8)*64 + col + 1] = acc[nf][3];
    }
}

__global__ void kv_reduce()
{
    int idx = blockIdx.x*256 + threadIdx.x;
    int bh = idx >> 12;
    int rem = idx & 4095;
    int m = rem >> 6, d = rem & 63;
    float s = 0.f;
    #pragma unroll
    for (int sp = 0; sp < 8; sp++)
        s += g_kvp[((long)(bh*8 + sp))*4096 + rem];
    g_kvth[(long)bh*4096 + d*64 + m] = __float2half_rn(s);
}

// =====================================================================
// FUSED o = q@kv + LayerNorm -> g_xh (fp16)  (unchanged)
// =====================================================================
#define FL_Q    0
#define FL_B    65536
#define FL_G    196608
#define FL_BE   200704
#define FL_PS   204800
#define FL_PQ   205824
#define FL_MU   206848
#define FL_INV  206976
#define FUSE_SMEM 207104
#define STG_W   1040

__global__ __launch_bounds__(256, 1)
void o_ln_fused(const float* __restrict__ gamma, const float* __restrict__ beta)
{
    extern __shared__ char smem[];
    const uint32_t sb = smem_u32(smem);
    const int tid = threadIdx.x;
    const int lane = tid & 31, wid = tid >> 5;
    const int b = blockIdx.x >> 7;
    const int n0 = (blockIdx.x & 127) * 32;

    {
        float4 g4 = ((const float4*)gamma)[tid];
        float4 b4 = ((const float4*)beta)[tid];
        *(float4*)(smem + FL_G  + tid*16) = g4;
        *(float4*)(smem + FL_BE + tid*16) = b4;
    }

    #pragma unroll
    for (int i = 0; i < 16; i++) {
        int cid = tid + i*256;
        int h = cid >> 8;
        int rr = (cid >> 3) & 31;
        int c16 = cid & 7;
        uint32_t off = rr*128 + c16*16;
        uint32_t sw = off ^ ((off >> 3) & 0x70);
        cpa16(sb + FL_Q + h*4096 + sw,
              g_qh + (((long)(b*16 + h))*SEQ + n0 + rr)*DHEAD + c16*8);
    }
    #pragma unroll
    for (int i = 0; i < 32; i++) {
        int cid = tid + i*256;
        int h = cid >> 9;
        int rr = (cid >> 3) & 63;
        int c16 = cid & 7;
        uint32_t off = rr*128 + c16*16;
        uint32_t sw = off ^ ((off >> 3) & 0x70);
        cpa16(sb + FL_B + h*8192 + sw,
              g_kvth + ((long)(b*16 + h))*4096 + rr*64 + c16*8);
    }
    CP_COMMIT(); CP_WAIT(0);
    __syncthreads();

    const int ra  = lane & 15;
    const int kba = ((lane >> 4) & 1) * 16;
    const int nnb = (lane & 7) + ((lane >> 4) & 1)*8;
    const int kbb = ((lane >> 3) & 1) * 16;

    float acc[2][2][8][4];
    #pragma unroll
    for (int a = 0; a < 2; a++)
        #pragma unroll
        for (int m = 0; m < 2; m++)
            #pragma unroll
            for (int n = 0; n < 8; n++)
                #pragma unroll
                for (int d = 0; d < 4; d++) acc[a][m][n][d] = 0.f;

    #pragma unroll
    for (int hl = 0; hl < 2; hl++) {
        const int h = wid*2 + hl;
        const uint32_t qa = sb + FL_Q + h*4096;
        const uint32_t ba = sb + FL_B + h*8192;
        #pragma unroll
        for (int k16 = 0; k16 < 4; k16++) {
            uint32_t af[2][4], bfr[4][4];
            #pragma unroll
            for (int mf = 0; mf < 2; mf++) {
                uint32_t off = (uint32_t)(mf*16 + ra)*128 + k16*32 + kba;
                uint32_t sw = off ^ ((off >> 3) & 0x70);
                ldm_x4(qa + sw, af[mf]);
            }
            #pragma unroll
            for (int np = 0; np < 4; np++) {
                uint32_t off = (uint32_t)(np*16 + nnb)*128 + k16*32 + kbb;
                uint32_t sw = off ^ ((off >> 3) & 0x70);
                ldm_x4(ba + sw, bfr[np]);
            }
            #pragma unroll
            for (int mf = 0; mf < 2; mf++)
                #pragma unroll
                for (int nf = 0; nf < 8; nf++)
                    mma16816h(acc[hl][mf][nf], af[mf], &bfr[nf >> 1][(nf & 1)*2]);
        }
    }

    float rs[4] = {0.f,0.f,0.f,0.f}, rq[4] = {0.f,0.f,0.f,0.f};
    #pragma unroll
    for (int hl = 0; hl < 2; hl++)
        #pragma unroll
        for (int nf = 0; nf < 8; nf++) {
            float a0 = acc[hl][0][nf][0], a1 = acc[hl][0][nf][1];
            float a2 = acc[hl][0][nf][2], a3 = acc[hl][0][nf][3];
            float c0 = acc[hl][1][nf][0], c1 = acc[hl][1][nf][1];
            float c2 = acc[hl][1][nf][2], c3 = acc[hl][1][nf][3];
            rs[0] += a0 + a1;  rq[0] += a0*a0 + a1*a1;
            rs[1] += a2 + a3;  rq[1] += a2*a2 + a3*a3;
            rs[2] += c0 + c1;  rq[2] += c0*c0 + c1*c1;
            rs[3] += c2 + c3;  rq[3] += c2*c2 + c3*c3;
        }
    #pragma unroll
    for (int o = 1; o < 4; o <<= 1) {
        #pragma unroll
        for (int i = 0; i < 4; i++) {
            rs[i] += __shfl_xor_sync(0xffffffffu, rs[i], o);
            rq[i] += __shfl_xor_sync(0xffffffffu, rq[i], o);
        }
    }
    float* ps = (float*)(smem + FL_PS) + wid*32;
    float* pq = (float*)(smem + FL_PQ) + wid*32;
    if ((lane & 3) == 0) {
        int r0 = lane >> 2;
        ps[r0]    = rs[0];  pq[r0]    = rq[0];
        ps[r0+8]  = rs[1];  pq[r0+8]  = rq[1];
        ps[r0+16] = rs[2];  pq[r0+16] = rq[2];
        ps[r0+24] = rs[3];  pq[r0+24] = rq[3];
    }
    __syncthreads();
    if (tid < 32) {
        float s = 0.f, q = 0.f;
        #pragma unroll
        for (int w = 0; w < 8; w++) {
            s += ((const float*)(smem + FL_PS))[w*32 + tid];
            q += ((const float*)(smem + FL_PQ))[w*32 + tid];
        }
        float mu = s * (1.f/INNER);
        float var = q * (1.f/INNER) - mu*mu;
        ((float*)(smem + FL_MU))[tid]  = mu;
        ((float*)(smem + FL_INV))[tid] = rsqrtf(fmaxf(var, 0.f) + LN_EPS);
    }
    __syncthreads();

    __half* stage = (__half*)smem;
    const float* muv = (const float*)(smem + FL_MU);
    const float* ivv = (const float*)(smem + FL_INV);
    const float* gam = (const float*)(smem + FL_G);
    const float* bet = (const float*)(smem + FL_BE);
    #pragma unroll
    for (int hl = 0; hl < 2; hl++) {
        const int h = wid*2 + hl;
        #pragma unroll
        for (int mf = 0; mf < 2; mf++) {
            int r0 = mf*16 + (lane >> 2);
            float mu0 = muv[r0],   iv0 = ivv[r0];
            float mu1 = muv[r0+8], iv1 = ivv[r0+8];
            #pragma unroll
            for (int nf = 0; nf < 8; nf++) {
                int gc = h*64 + nf*8 + (lane & 3)*2;
                float g0 = gam[gc], g1 = gam[gc+1];
                float b0 = bet[gc], b1 = bet[gc+1];
                const float* a = acc[hl][mf][nf];
                __half2 p0 = __halves2half2(
                    __float2half_rn((a[0]-mu0)*iv0*g0 + b0),
                    __float2half_rn((a[1]-mu0)*iv0*g1 + b1));
                __half2 p1 = __halves2half2(
                    __float2half_rn((a[2]-mu1)*iv1*g0 + b0),
                    __float2half_rn((a[3]-mu1)*iv1*g1 + b1));
                *(__half2*)(stage + r0*STG_W + gc)     = p0;
                *(__half2*)(stage + (r0+8)*STG_W + gc) = p1;
            }
        }
    }
    __syncthreads();

    #pragma unroll
    for (int i = 0; i < 16; i++) {
        int idx = tid + i*256;
        int row = idx >> 7, c = idx & 127;
        uint4 v = *(const uint4*)(stage + row*STG_W + c*8);
        *(uint4*)(g_xh + ((long)(b*SEQ + n0 + row))*INNER + c*8) = v;
    }
}

// =====================================================================
// launcher
// =====================================================================
extern "C" void kernel_launch(void* const* d_in, const int* in_sizes, int n_in,
                              void* d_out, int out_size)
{
    const float* x     = (const float*)d_in[0];
    const float* w_qkv = (const float*)d_in[1];
    const float* gamma = (const float*)d_in[2];
    const float* beta  = (const float*)d_in[3];
    const float* w_out = (const float*)d_in[4];
    const float* b_out = (const float*)d_in[5];
    float* out = (float*)d_out;

    cudaFuncSetAttribute(mma_gemm, cudaFuncAttributeMaxDynamicSharedMemorySize, GEMM_SMEM);
    cudaFuncSetAttribute(o_ln_fused, cudaFuncAttributeMaxDynamicSharedMemorySize, FUSE_SMEM);

    cvt_all<<<NBX + NB1 + NB2, 256>>>(x, w_qkv, w_out);

    mma_gemm<<<dim3(QKVN/128, MROWS/128), 256, GEMM_SMEM>>>(nullptr, nullptr, 0);
    kv_partial<<<512, 256>>>();
    kv_reduce<<<1024, 256>>>();
    o_ln_fused<<<512, 256, FUSE_SMEM>>>(gamma, beta);
    mma_gemm<<<dim3(DIM/128, MROWS/128), 256, GEMM_SMEM>>>(b_out, out, 1);
}